// round 5
// baseline (speedup 1.0000x reference)
#include <cuda_runtime.h>
#include <cuda_bf16.h>

// DPLoss: mean over B rows of [ sum_{j<len[i]} (pred[i,j]-log(align[i,j]))^2 / len[i] ]
// B=4096, T=2048, fp32. HBM-bound (~67 MB, floor ~8.4us @ 8TB/s).
//
// R5: single-wave grid (1184 CTAs) + flat thread-level striding (<=2% tail)
// + unroll-by-2 with all 4 LDG.128 front-batched (MLP_p1>=4, the variable
// that R1-vs-R3 proved controls DRAM%). Reg cap 42 (6 CTA/SM).

#define B_ROWS   4096
#define T_COLS   2048
#define T_VEC4   (T_COLS / 4)              // 512 float4 per row
#define NV4      (B_ROWS * T_VEC4)         // 2,097,152 float4 per tensor
#define NTHREADS 256
#define NCTAS    1184                      // 148 SMs, single wave
#define STRIDE   (NCTAS * NTHREADS)        // 303,104

__device__ float    g_acc = 0.0f;
__device__ unsigned g_count = 0;

// Per-float4 contribution: masked squared error scaled by 1/len.
__device__ __forceinline__ float unit_term(float4 pv, float4 av, int i,
                                           const int* __restrict__ lens)
{
    const int row = i >> 9;                 // i / 512
    const int len = __ldg(lens + row);      // 16KB, L1-resident
    const int j   = (i & 511) << 2;         // element index within row

    float d0 = pv.x - __logf(av.x);
    float d1 = pv.y - __logf(av.y);
    float d2 = pv.z - __logf(av.z);
    float d3 = pv.w - __logf(av.w);

    float rs = 0.0f;
    if (j + 0 < len) rs += d0 * d0;
    if (j + 1 < len) rs += d1 * d1;
    if (j + 2 < len) rs += d2 * d2;
    if (j + 3 < len) rs += d3 * d3;

    return rs * __fdividef(1.0f, (float)len);
}

__global__ __launch_bounds__(NTHREADS, 6) void dploss_kernel(
    const float4* __restrict__ pred,
    const float4* __restrict__ align,
    const int* __restrict__ lens,
    float* __restrict__ out)
{
    int i = blockIdx.x * NTHREADS + threadIdx.x;
    float s = 0.0f;

    // 6 unconditional iterations (valid for all threads: max base + 5*STRIDE < NV4),
    // as 3 pairs with all 4 LDG.128 issued before any compute.
    #pragma unroll
    for (int p = 0; p < 3; ++p) {
        const int i0 = i;
        const int i1 = i + STRIDE;
        float4 pv0 = pred[i0];
        float4 av0 = align[i0];
        float4 pv1 = pred[i1];
        float4 av1 = align[i1];
        s += unit_term(pv0, av0, i0, lens);
        s += unit_term(pv1, av1, i1, lens);
        i += 2 * STRIDE;
    }

    // guarded 7th iteration
    if (i < NV4) {
        float4 pv = pred[i];
        float4 av = align[i];
        s += unit_term(pv, av, i, lens);
    }

    // warp reduction
    #pragma unroll
    for (int off = 16; off > 0; off >>= 1)
        s += __shfl_down_sync(0xFFFFFFFFu, s, off);

    // block reduction across 8 warps
    __shared__ float warp_sums[NTHREADS / 32];
    const int wid = threadIdx.x >> 5;
    const int lid = threadIdx.x & 31;
    if (lid == 0) warp_sums[wid] = s;
    __syncthreads();

    if (wid == 0) {
        float v = (lid < NTHREADS / 32) ? warp_sums[lid] : 0.0f;
        #pragma unroll
        for (int off = 4; off > 0; off >>= 1)
            v += __shfl_down_sync(0xFFFFFFFFu, v, off);

        if (lid == 0) {
            atomicAdd(&g_acc, v);
            __threadfence();
            unsigned prev = atomicInc(&g_count, NCTAS - 1);
            if (prev == NCTAS - 1) {
                float total = atomicExch(&g_acc, 0.0f);   // read + reset for replay
                *out = total * (1.0f / (float)B_ROWS);
            }
        }
    }
}

extern "C" void kernel_launch(void* const* d_in, const int* in_sizes, int n_in,
                              void* d_out, int out_size)
{
    const float4* pred  = (const float4*)d_in[0];
    const float4* align = (const float4*)d_in[1];
    const int*    lens  = (const int*)d_in[2];
    float* out = (float*)d_out;

    dploss_kernel<<<NCTAS, NTHREADS>>>(pred, align, lens, out);
}